// round 11
// baseline (speedup 1.0000x reference)
#include <cuda_runtime.h>
#include <cfloat>

// PoolingLayer: out[p, f] = max_k features[neighbor_indices[p, k], f]
// N=100000, NP=50000, K=32, F=128
// Inputs: points (N,3) f32 [unused], features (N,128) f32,
//         neighbor_indices (NP,32) int32. Output (NP,128) f32.
//
// LTS-bound random gather at ~72% of L2 peak (plateau across all variants).
// One warp per point; lane covers a 32-byte (8-float) slot; 16 lanes span a
// 512B feature row, so ONE ld.global.v8 (LDG.256, sm_100+) fetches TWO
// neighbor rows. This round: (a) two independent acc chains to trim regs /
// raise occupancy, (b) L2::evict_last on feature loads so the 51MB
// L2-resident table wins residency against streaming refills.

#define NPTS   100000
#define NP_OUT 50000
#define KNBR   32
#define FDIM   128            // 512 bytes per feature row

__device__ __forceinline__ void ldg256_el(const char* p, float* v) {
    asm volatile("ld.global.L2::evict_last.v8.f32 {%0,%1,%2,%3,%4,%5,%6,%7}, [%8];"
                 : "=f"(v[0]), "=f"(v[1]), "=f"(v[2]), "=f"(v[3]),
                   "=f"(v[4]), "=f"(v[5]), "=f"(v[6]), "=f"(v[7])
                 : "l"(p));
}

__device__ __forceinline__ void stg256(char* p, const float* v) {
    asm volatile("st.global.v8.f32 [%0], {%1,%2,%3,%4,%5,%6,%7,%8};"
                 :: "l"(p),
                    "f"(v[0]), "f"(v[1]), "f"(v[2]), "f"(v[3]),
                    "f"(v[4]), "f"(v[5]), "f"(v[6]), "f"(v[7])
                 : "memory");
}

__global__ __launch_bounds__(256)
void pool_max_kernel(const char* __restrict__ feats_b,   // features base (bytes)
                     const int* __restrict__ nbr,        // (NP, 32) int32
                     char* __restrict__ out_b)            // (NP, 128) f32 (bytes)
{
    const int gtid = blockIdx.x * blockDim.x + threadIdx.x;
    const int warp = gtid >> 5;          // one warp per output point
    const int lane = gtid & 31;
    if (warp >= NP_OUT) return;

    const int half = lane >> 4;          // 0: even rows, 1: odd rows
    const int m    = lane & 15;          // 32-byte slot within the row

    // Coalesced load of the 32 neighbor indices, pre-scaled to byte offsets.
    const int my_idx = nbr[(size_t)warp * KNBR + lane];
    const int my_off = my_idx << 9;      // *512 bytes per row

    const char* base = feats_b + (m << 5);   // + slot*32 bytes

    float acc0[8], acc1[8];
    #pragma unroll
    for (int j = 0; j < 8; j++) { acc0[j] = -FLT_MAX; acc1[j] = -FLT_MAX; }

    // 32 neighbors, 4 rows per batch via 2 LDG.256 in flight,
    // two independent max chains (register-friendly).
    #pragma unroll
    for (int k = 0; k < KNBR; k += 4) {
        const int oA = __shfl_sync(0xffffffffu, my_off, k + half);      // rows k / k+1
        const int oB = __shfl_sync(0xffffffffu, my_off, k + 2 + half);  // rows k+2 / k+3
        float va[8], vb[8];
        ldg256_el(base + oA, va);
        ldg256_el(base + oB, vb);
        #pragma unroll
        for (int j = 0; j < 8; j++) acc0[j] = fmaxf(acc0[j], va[j]);
        #pragma unroll
        for (int j = 0; j < 8; j++) acc1[j] = fmaxf(acc1[j], vb[j]);
    }

    // Merge the two chains, then combine even-row half with odd-row half:
    // the same column slot lives in lane m and lane m+16.
    #pragma unroll
    for (int j = 0; j < 8; j++) {
        acc0[j] = fmaxf(acc0[j], acc1[j]);
        const float o = __shfl_xor_sync(0xffffffffu, acc0[j], 16);
        acc0[j] = fmaxf(acc0[j], o);
    }

    // Lanes 0..15 write the 512B output row with STG.256.
    if (half == 0) {
        stg256(out_b + (size_t)warp * (FDIM * 4) + (m << 5), acc0);
    }
}

extern "C" void kernel_launch(void* const* d_in, const int* in_sizes, int n_in,
                              void* d_out, int out_size) {
    // d_in[0] = points (unused), d_in[1] = features, d_in[2] = neighbor_indices
    const char* feats = (const char*)d_in[1];
    const int* nbr = (const int*)d_in[2];
    char* out = (char*)d_out;

    const int total_threads = NP_OUT * 32;      // one warp per output point
    const int block = 256;
    const int grid = (total_threads + block - 1) / block;
    pool_max_kernel<<<grid, block>>>(feats, nbr, out);
}

// round 12
// speedup vs baseline: 1.1467x; 1.1467x over previous
#include <cuda_runtime.h>
#include <cfloat>

// PoolingLayer: out[p, f] = max_k features[neighbor_indices[p, k], f]
// N=100000, NP=50000, K=32, F=128
// Inputs: points (N,3) f32 [unused], features (N,128) f32,
//         neighbor_indices (NP,32) int32. Output (NP,128) f32.
//
// FINAL (R9 form, best measured 45.54us): LTS-bound random gather at the
// ~72%-of-peak L2 service plateau (~17.5 TB/s achieved). Traffic (819MB of
// random 512B-row reads) is irreducible; occupancy / MLP / cache-hint /
// instruction-count variations all land 45.5-55us, with this form fastest.
//
// Layout: one warp per point; lane covers a 32-byte (8-float) slot; 16 lanes
// span a 512B feature row, so ONE ld.global.v8 (LDG.256, sm_100+) fetches
// TWO neighbor rows (lower half-warp row k, upper half row k+1). Halves the
// gather/store instruction count vs float4. Cross-half max via shfl_xor(16).

#define NPTS   100000
#define NP_OUT 50000
#define KNBR   32
#define FDIM   128            // 512 bytes per feature row

__device__ __forceinline__ void ldg256(const char* p, float* v) {
    asm volatile("ld.global.v8.f32 {%0,%1,%2,%3,%4,%5,%6,%7}, [%8];"
                 : "=f"(v[0]), "=f"(v[1]), "=f"(v[2]), "=f"(v[3]),
                   "=f"(v[4]), "=f"(v[5]), "=f"(v[6]), "=f"(v[7])
                 : "l"(p));
}

__device__ __forceinline__ void stg256(char* p, const float* v) {
    asm volatile("st.global.v8.f32 [%0], {%1,%2,%3,%4,%5,%6,%7,%8};"
                 :: "l"(p),
                    "f"(v[0]), "f"(v[1]), "f"(v[2]), "f"(v[3]),
                    "f"(v[4]), "f"(v[5]), "f"(v[6]), "f"(v[7])
                 : "memory");
}

__global__ __launch_bounds__(256)
void pool_max_kernel(const char* __restrict__ feats_b,   // features base (bytes)
                     const int* __restrict__ nbr,        // (NP, 32) int32
                     char* __restrict__ out_b)            // (NP, 128) f32 (bytes)
{
    const int gtid = blockIdx.x * blockDim.x + threadIdx.x;
    const int warp = gtid >> 5;          // one warp per output point
    const int lane = gtid & 31;
    if (warp >= NP_OUT) return;

    const int half = lane >> 4;          // 0: even rows, 1: odd rows
    const int m    = lane & 15;          // 32-byte slot within the row

    // Coalesced load of the 32 neighbor indices, pre-scaled to byte offsets.
    const int my_idx = nbr[(size_t)warp * KNBR + lane];
    const int my_off = my_idx << 9;      // *512 bytes per row

    const char* base = feats_b + (m << 5);   // + slot*32 bytes

    float acc[8];
    #pragma unroll
    for (int j = 0; j < 8; j++) acc[j] = -FLT_MAX;

    // 32 neighbors, 4 rows per batch via 2 LDG.256 in flight.
    #pragma unroll
    for (int k = 0; k < KNBR; k += 4) {
        const int oA = __shfl_sync(0xffffffffu, my_off, k + half);      // rows k / k+1
        const int oB = __shfl_sync(0xffffffffu, my_off, k + 2 + half);  // rows k+2 / k+3
        float va[8], vb[8];
        ldg256(base + oA, va);
        ldg256(base + oB, vb);
        #pragma unroll
        for (int j = 0; j < 8; j++)
            acc[j] = fmaxf(acc[j], fmaxf(va[j], vb[j]));
    }

    // Combine lower-half (even rows) with upper-half (odd rows): same column
    // slot lives in lane m and lane m+16.
    #pragma unroll
    for (int j = 0; j < 8; j++) {
        const float o = __shfl_xor_sync(0xffffffffu, acc[j], 16);
        acc[j] = fmaxf(acc[j], o);
    }

    // Lanes 0..15 write the 512B output row with STG.256.
    if (half == 0) {
        stg256(out_b + (size_t)warp * (FDIM * 4) + (m << 5), acc);
    }
}

extern "C" void kernel_launch(void* const* d_in, const int* in_sizes, int n_in,
                              void* d_out, int out_size) {
    // d_in[0] = points (unused), d_in[1] = features, d_in[2] = neighbor_indices
    const char* feats = (const char*)d_in[1];
    const int* nbr = (const int*)d_in[2];
    char* out = (char*)d_out;

    const int total_threads = NP_OUT * 32;      // one warp per output point
    const int block = 256;
    const int grid = (total_threads + block - 1) / block;
    pool_max_kernel<<<grid, block>>>(feats, nbr, out);
}

// round 13
// speedup vs baseline: 1.2205x; 1.0643x over previous
#include <cuda_runtime.h>
#include <cfloat>

// PoolingLayer: out[p, f] = max_k features[neighbor_indices[p, k], f]
// N=100000, NP=50000, K=32, F=128
// Inputs: points (N,3) f32 [unused], features (N,128) f32,
//         neighbor_indices (NP,32) int32. Output (NP,128) f32.
//
// LTS-bound random gather at the L2 service plateau (~72% of peak; run-to-run
// noise +-2us). R9 layout (best): one warp per point; lane covers a 32-byte
// (8-float) slot; 16 lanes span a 512B row, so ONE ld.global.v8 (LDG.256)
// fetches TWO neighbor rows. This round's single surgical change: output
// stores use st.global.cs (evict-first) so the 25.6MB/launch single-use
// output stream stops evicting the L2-resident 51MB feature table across
// graph replays (~40MB/launch of table refills observed as 20% DRAM).
// Store hints cost zero registers, so the proven R9 codegen is preserved.

#define NPTS   100000
#define NP_OUT 50000
#define KNBR   32
#define FDIM   128            // 512 bytes per feature row

__device__ __forceinline__ void ldg256(const char* p, float* v) {
    asm volatile("ld.global.v8.f32 {%0,%1,%2,%3,%4,%5,%6,%7}, [%8];"
                 : "=f"(v[0]), "=f"(v[1]), "=f"(v[2]), "=f"(v[3]),
                   "=f"(v[4]), "=f"(v[5]), "=f"(v[6]), "=f"(v[7])
                 : "l"(p));
}

__device__ __forceinline__ void stg256_cs(char* p, const float* v) {
    asm volatile("st.global.cs.v8.f32 [%0], {%1,%2,%3,%4,%5,%6,%7,%8};"
                 :: "l"(p),
                    "f"(v[0]), "f"(v[1]), "f"(v[2]), "f"(v[3]),
                    "f"(v[4]), "f"(v[5]), "f"(v[6]), "f"(v[7])
                 : "memory");
}

__global__ __launch_bounds__(256)
void pool_max_kernel(const char* __restrict__ feats_b,   // features base (bytes)
                     const int* __restrict__ nbr,        // (NP, 32) int32
                     char* __restrict__ out_b)            // (NP, 128) f32 (bytes)
{
    const int gtid = blockIdx.x * blockDim.x + threadIdx.x;
    const int warp = gtid >> 5;          // one warp per output point
    const int lane = gtid & 31;
    if (warp >= NP_OUT) return;

    const int half = lane >> 4;          // 0: even rows, 1: odd rows
    const int m    = lane & 15;          // 32-byte slot within the row

    // Coalesced load of the 32 neighbor indices, pre-scaled to byte offsets.
    const int my_idx = nbr[(size_t)warp * KNBR + lane];
    const int my_off = my_idx << 9;      // *512 bytes per row

    const char* base = feats_b + (m << 5);   // + slot*32 bytes

    float acc[8];
    #pragma unroll
    for (int j = 0; j < 8; j++) acc[j] = -FLT_MAX;

    // 32 neighbors, 4 rows per batch via 2 LDG.256 in flight.
    #pragma unroll
    for (int k = 0; k < KNBR; k += 4) {
        const int oA = __shfl_sync(0xffffffffu, my_off, k + half);      // rows k / k+1
        const int oB = __shfl_sync(0xffffffffu, my_off, k + 2 + half);  // rows k+2 / k+3
        float va[8], vb[8];
        ldg256(base + oA, va);
        ldg256(base + oB, vb);
        #pragma unroll
        for (int j = 0; j < 8; j++)
            acc[j] = fmaxf(acc[j], fmaxf(va[j], vb[j]));
    }

    // Combine lower-half (even rows) with upper-half (odd rows): same column
    // slot lives in lane m and lane m+16.
    #pragma unroll
    for (int j = 0; j < 8; j++) {
        const float o = __shfl_xor_sync(0xffffffffu, acc[j], 16);
        acc[j] = fmaxf(acc[j], o);
    }

    // Lanes 0..15 write the 512B output row with STG.256 (evict-first).
    if (half == 0) {
        stg256_cs(out_b + (size_t)warp * (FDIM * 4) + (m << 5), acc);
    }
}

extern "C" void kernel_launch(void* const* d_in, const int* in_sizes, int n_in,
                              void* d_out, int out_size) {
    // d_in[0] = points (unused), d_in[1] = features, d_in[2] = neighbor_indices
    const char* feats = (const char*)d_in[1];
    const int* nbr = (const int*)d_in[2];
    char* out = (char*)d_out;

    const int total_threads = NP_OUT * 32;      // one warp per output point
    const int block = 256;
    const int grid = (total_threads + block - 1) / block;
    pool_max_kernel<<<grid, block>>>(feats, nbr, out);
}